// round 5
// baseline (speedup 1.0000x reference)
#include <cuda_runtime.h>

// Problem constants
#define BQ    4
#define CCH   2
#define SLEN  4096
#define KW    64
#define NKF   32
#define OUTC  512
#define TDIM  72        // padded t-range; valid t = 0..64
#define KSPLIT 16
#define QCHUNK 256      // K (=q) elements per split-K block (power of 2)
#define XSLEN  608      // max ring-refill index 591, padded + aligned
#define SWROW 36        // padded swT row (floats)

// Scratch (device globals: no allocations allowed)
__device__ float g_Tpart[KSPLIT * BQ * OUTC * TDIM];   // 9.4 MB partials
__device__ float g_Tred[BQ * OUTC * TDIM];

// ---- packed f32x2 helpers (sm_100+; 2x FFMA lane throughput) ----
__device__ __forceinline__ unsigned long long pack2(float a, float b) {
    unsigned long long r;
    asm("mov.b64 %0, {%1, %2};" : "=l"(r) : "f"(a), "f"(b));
    return r;
}
__device__ __forceinline__ void ffma2(unsigned long long& d, unsigned long long a, unsigned long long b) {
    asm("fma.rn.f32x2 %0, %1, %2, %0;" : "+l"(d) : "l"(a), "l"(b));
}
__device__ __forceinline__ float2 unpack2(unsigned long long v) {
    float2 r;
    asm("mov.b64 {%0, %1}, %2;" : "=f"(r.x), "=f"(r.y) : "l"(v));
    return r;
}

// One k-step J (within group): both o-rows, 4 t-pairs against ring R[J..J+3]
#define STEP(J, WA, WB) do {                                          \
    unsigned long long pa_ = pack2((WA), (WA));                       \
    unsigned long long pb_ = pack2((WB), (WB));                       \
    ffma2(accA0, pa_, R[(J) & 7]);   ffma2(accA1, pa_, R[((J)+1) & 7]); \
    ffma2(accA2, pa_, R[((J)+2) & 7]); ffma2(accA3, pa_, R[((J)+3) & 7]); \
    ffma2(accB0, pb_, R[(J) & 7]);   ffma2(accB1, pb_, R[((J)+1) & 7]); \
    ffma2(accB2, pb_, R[((J)+2) & 7]); ffma2(accB3, pb_, R[((J)+3) & 7]); \
} while (0)

// 8 k-steps using weight regs C*, prefetching next group's weights into N*.
// Ring invariant: at entry R[i] = x pair (kk0+i); each refill replaces a pair
// right after its last use, so at exit R[i] = pair (kk0+8+i). Window advances
// 8 pairs (16 floats) per group -> FOUR LDS.128 refills per group:
//   after STEP(1): R[0],R[1] <- pairs kk0+8,  kk0+9   (xs + 2*kk0+t0+16)
//   after STEP(3): R[2],R[3] <- pairs kk0+10, kk0+11  (xs + 2*kk0+t0+20)
//   after STEP(5): R[4],R[5] <- pairs kk0+12, kk0+13  (xs + 2*kk0+t0+24)
//   after STEP(7): R[6],R[7] <- pairs kk0+14, kk0+15  (xs + 2*kk0+t0+28)
#define GROUP8(K0, C0A, C1A, C0B, C1B, N0A, N1A, N0B, N1B) do {       \
    int nk_ = ((K0) + 8) & (QCHUNK - 1);                              \
    N0A = __ldg((const float4*)(w0 + nk_));                           \
    N0B = __ldg((const float4*)(w1 + nk_));                           \
    N1A = __ldg((const float4*)(w0 + nk_ + 4));                       \
    N1B = __ldg((const float4*)(w1 + nk_ + 4));                       \
    STEP(0, C0A.x, C0B.x);                                            \
    STEP(1, C0A.y, C0B.y);                                            \
    { ulonglong2 t_ = *(const ulonglong2*)&xs[2*(K0) + t0 + 16];      \
      R[0] = t_.x; R[1] = t_.y; }                                     \
    STEP(2, C0A.z, C0B.z);                                            \
    STEP(3, C0A.w, C0B.w);                                            \
    { ulonglong2 t_ = *(const ulonglong2*)&xs[2*(K0) + t0 + 20];      \
      R[2] = t_.x; R[3] = t_.y; }                                     \
    STEP(4, C1A.x, C1B.x);                                            \
    STEP(5, C1A.y, C1B.y);                                            \
    { ulonglong2 t_ = *(const ulonglong2*)&xs[2*(K0) + t0 + 24];      \
      R[4] = t_.x; R[5] = t_.y; }                                     \
    STEP(6, C1A.z, C1B.z);                                            \
    STEP(7, C1A.w, C1B.w);                                            \
    { ulonglong2 t_ = *(const ulonglong2*)&xs[2*(K0) + t0 + 28];      \
      R[6] = t_.x; R[7] = t_.y; }                                     \
} while (0)

// ============================================================================
// Kernel A: partial strided-correlation GEMM
//   Tpart[kc][b][o][t] = sum over this block's q-chunk of
//       conv_w[o, c*2048+q] * xpad[b, c, 2q+t]
// Block: 288 threads (9 warps) = 32 o-rows x 9 t-cols. Thread: 2o x 8t.
// x window lives in an 8-pair register RING (no shift MOVs, 4 LDS.128 per
// 8 k-steps). Weights: gmem float4 streams, 8-step ping-pong prefetch.
// ============================================================================
__global__ __launch_bounds__(288, 2)
void gemm_partial_kernel(const float* __restrict__ x,
                         const float* __restrict__ conv_w) {
    __shared__ __align__(16) float xs[XSLEN];

    const int otile = blockIdx.x;   // 0..7  -> 64 o's each
    const int b     = blockIdx.y;   // 0..3
    const int kc    = blockIdx.z;   // 0..15 -> 256 q each

    const int tid = threadIdx.x;
    const int k0  = kc * QCHUNK;
    const int ci  = k0 >> 11;       // channel for this chunk
    const int qq0 = k0 & 2047;      // q offset within channel
    const int obase = otile * 64;

    // Stage x slice: xs[j] = xpad[b, ci, 2*qq0 + j]
    const float* xrow = x + (b * CCH + ci) * SLEN;
    for (int i = tid; i < XSLEN; i += 288) {
        int g = 2 * qq0 + i;
        xs[i] = (g < SLEN) ? xrow[g] : 0.0f;
    }

    const int row  = tid / 9;        // 0..31
    const int col  = tid - row * 9;  // 0..8
    const int t0   = col * 8;        // 0,8,...,64
    const int row2 = row * 2;

    __syncthreads();

    // init ring: pairs 0..7 cover xs[t0 .. t0+15]
    unsigned long long R[8];
    { ulonglong2 v = *(const ulonglong2*)&xs[t0];      R[0]=v.x; R[1]=v.y; }
    { ulonglong2 v = *(const ulonglong2*)&xs[t0 + 4];  R[2]=v.x; R[3]=v.y; }
    { ulonglong2 v = *(const ulonglong2*)&xs[t0 + 8];  R[4]=v.x; R[5]=v.y; }
    { ulonglong2 v = *(const ulonglong2*)&xs[t0 + 12]; R[6]=v.x; R[7]=v.y; }

    unsigned long long accA0=0, accA1=0, accA2=0, accA3=0;
    unsigned long long accB0=0, accB1=0, accB2=0, accB3=0;

    const float* w0 = conv_w + (size_t)(obase + row2) * 4096 + k0;
    const float* w1 = w0 + 4096;

    float4 a0A = __ldg((const float4*)(w0));
    float4 a1A = __ldg((const float4*)(w0 + 4));
    float4 a0B = __ldg((const float4*)(w1));
    float4 a1B = __ldg((const float4*)(w1 + 4));
    float4 b0A, b1A, b0B, b1B;

    #pragma unroll 1
    for (int kk0 = 0; kk0 < QCHUNK; kk0 += 16) {
        GROUP8(kk0,     a0A, a1A, a0B, a1B, b0A, b1A, b0B, b1B);
        GROUP8(kk0 + 8, b0A, b1A, b0B, b1B, a0A, a1A, a0B, a1B);
    }

    // write partials: Tpart[kc][b][o][t]
    float* tp = g_Tpart + ((size_t)(kc * BQ + b) * OUTC) * TDIM;
    {
        float* dst = tp + (size_t)(obase + row2) * TDIM + t0;
        float2 v;
        v = unpack2(accA0); dst[0] = v.x; dst[1] = v.y;
        v = unpack2(accA1); dst[2] = v.x; dst[3] = v.y;
        v = unpack2(accA2); dst[4] = v.x; dst[5] = v.y;
        v = unpack2(accA3); dst[6] = v.x; dst[7] = v.y;
        dst += TDIM;
        v = unpack2(accB0); dst[0] = v.x; dst[1] = v.y;
        v = unpack2(accB1); dst[2] = v.x; dst[3] = v.y;
        v = unpack2(accB2); dst[4] = v.x; dst[5] = v.y;
        v = unpack2(accB3); dst[6] = v.x; dst[7] = v.y;
    }
}

// ============================================================================
// Kernel B: split-K reduction (fully coalesced)
// ============================================================================
__global__ __launch_bounds__(256)
void reduce_kernel() {
    int i = blockIdx.x * 256 + threadIdx.x;   // grid sized exactly
    float s = 0.0f;
    #pragma unroll
    for (int ks = 0; ks < KSPLIT; ks++)
        s += g_Tpart[(size_t)ks * (BQ * OUTC * TDIM) + i];
    g_Tred[i] = s;
}

// ============================================================================
// Kernel C: epilogue (4 bo per block)
//   out[b,o, p*2048 + m*32 + l] = relu( stft_w[l,m] * T[b,o,p+m] + conv_b[o] )
// ============================================================================
#define BO_PER_BLK 4
__global__ __launch_bounds__(256)
void epilogue_kernel(const float* __restrict__ stft_w,
                     const float* __restrict__ conv_b,
                     float* __restrict__ out) {
    __shared__ __align__(16) float swT[64 * SWROW];   // transposed: swT[m*36 + l]
    __shared__ float Ts[BO_PER_BLK * TDIM];           // 288
    __shared__ float biasS[BO_PER_BLK];

    const int bo0 = blockIdx.x * BO_PER_BLK;
    const int tid = threadIdx.x;

    for (int i = tid; i < 2048; i += 256) {
        int l = i >> 6, m = i & 63;
        swT[m * SWROW + l] = stft_w[i];
    }
    for (int i = tid; i < BO_PER_BLK * TDIM; i += 256)
        Ts[i] = g_Tred[(size_t)bo0 * TDIM + i];
    if (tid < BO_PER_BLK)
        biasS[tid] = conv_b[(bo0 + tid) & (OUTC - 1)];
    __syncthreads();

    #pragma unroll
    for (int jb = 0; jb < BO_PER_BLK; jb++) {
        const float bias = biasS[jb];
        float4* out4 = (float4*)(out + (size_t)(bo0 + jb) * 4096);
        const float* TsRow = &Ts[jb * TDIM];
        #pragma unroll
        for (int it = 0; it < 4; it++) {
            int q  = tid + it * 256;      // quad index; s' = 4*q
            int sp = q * 4;
            int p  = sp >> 11;
            int m  = (sp >> 5) & 63;
            int l0 = sp & 31;             // multiple of 4
            float tv = TsRow[p + m];
            float4 sw = *(const float4*)&swT[m * SWROW + l0];
            float4 r;
            r.x = fmaxf(fmaf(sw.x, tv, bias), 0.0f);
            r.y = fmaxf(fmaf(sw.y, tv, bias), 0.0f);
            r.z = fmaxf(fmaf(sw.z, tv, bias), 0.0f);
            r.w = fmaxf(fmaf(sw.w, tv, bias), 0.0f);
            out4[q] = r;
        }
    }
}

// ============================================================================
extern "C" void kernel_launch(void* const* d_in, const int* in_sizes, int n_in,
                              void* d_out, int out_size) {
    const float* x      = nullptr;
    const float* stft_w = nullptr;
    const float* conv_w = nullptr;
    const float* conv_b = nullptr;
    for (int i = 0; i < n_in; i++) {
        switch (in_sizes[i]) {
            case BQ * CCH * SLEN:  x      = (const float*)d_in[i]; break;  // 32768
            case NKF * KW:         stft_w = (const float*)d_in[i]; break;  // 2048
            case OUTC * 4096:      conv_w = (const float*)d_in[i]; break;  // 2097152
            case OUTC:             conv_b = (const float*)d_in[i]; break;  // 512
        }
    }

    gemm_partial_kernel<<<dim3(8, BQ, KSPLIT), 288>>>(x, conv_w);
    reduce_kernel<<<(BQ * OUTC * TDIM) / 256, 256>>>();
    epilogue_kernel<<<(BQ * OUTC) / BO_PER_BLK, 256>>>(stft_w, conv_b, (float*)d_out);
}

// round 6
// speedup vs baseline: 1.1208x; 1.1208x over previous
#include <cuda_runtime.h>

// Problem constants
#define BQ    4
#define CCH   2
#define SLEN  4096
#define KW    64
#define NKF   32
#define OUTC  512
#define TDIM  72        // padded t-range; valid t = 0..64
#define KSPLIT 16
#define QCHUNK 256      // K (=q) elements per split-K block
#define KTILE  32       // k per cp.async staging tile (8 tiles per chunk)
#define XSLEN  608      // raw x-slice length (max refill idx 590)
#define XSPLEN 648      // padded: f(607) = 643
#define WS_STRIDE 44    // floats per o-row in weight smem (16B-aligned, bank-spread)
#define WS_BUF (64 * WS_STRIDE)
#define SWROW 36        // padded swT row (floats)

// Scratch (device globals: no allocations allowed)
__device__ float g_Tpart[KSPLIT * BQ * OUTC * TDIM];   // 9.4 MB partials
__device__ float g_Tred[BQ * OUTC * TDIM];

// ---- packed f32x2 helpers (sm_100+; 2x FFMA lane throughput) ----
__device__ __forceinline__ unsigned long long pack2(float a, float b) {
    unsigned long long r;
    asm("mov.b64 %0, {%1, %2};" : "=l"(r) : "f"(a), "f"(b));
    return r;
}
__device__ __forceinline__ void ffma2(unsigned long long& d, unsigned long long a, unsigned long long b) {
    asm("fma.rn.f32x2 %0, %1, %2, %0;" : "+l"(d) : "l"(a), "l"(b));
}
__device__ __forceinline__ float2 unpack2(unsigned long long v) {
    float2 r;
    asm("mov.b64 {%0, %1}, %2;" : "=f"(r.x), "=f"(r.y) : "l"(v));
    return r;
}
__device__ __forceinline__ unsigned smem_u32(const void* p) {
    return (unsigned)__cvta_generic_to_shared(p);
}
__device__ __forceinline__ void cp_async16(unsigned dst, const void* src) {
    asm volatile("cp.async.cg.shared.global [%0], [%1], 16;" :: "r"(dst), "l"(src));
}
#define CP_COMMIT()  asm volatile("cp.async.commit_group;")
#define CP_WAIT1()   asm volatile("cp.async.wait_group 1;")

// padded x index: +2 floats per 32 (kills the col-0/4/8 bank collision)
#define XF(a) ((a) + (((a) >> 5) << 1))

// One k-step J (within group): both o-rows, 4 t-pairs against ring R[J..J+3]
#define STEP(J, WA, WB) do {                                          \
    unsigned long long pa_ = pack2((WA), (WA));                       \
    unsigned long long pb_ = pack2((WB), (WB));                       \
    ffma2(accA0, pa_, R[(J) & 7]);   ffma2(accA1, pa_, R[((J)+1) & 7]); \
    ffma2(accA2, pa_, R[((J)+2) & 7]); ffma2(accA3, pa_, R[((J)+3) & 7]); \
    ffma2(accB0, pb_, R[(J) & 7]);   ffma2(accB1, pb_, R[((J)+1) & 7]); \
    ffma2(accB2, pb_, R[((J)+2) & 7]); ffma2(accB3, pb_, R[((J)+3) & 7]); \
} while (0)

// ring refill: R[j] <- x pair at raw index 2*K0 + t0 + 16 + 2*j  (LDS.64, padded)
#define REFILL(K0, J) do {                                            \
    int ra_ = 2 * (K0) + t0 + 16 + 2 * (J);                           \
    R[J] = *(const unsigned long long*)&xsp[XF(ra_)];                 \
} while (0)

// 8 k-steps; weights from smem tile buffer (broadcast LDS.128).
// KL = local k offset within tile (0,8,16,24). Ring invariant as before:
// each refill replaces a pair right after its last use.
#define GROUP8S(K0, KL) do {                                          \
    float4 c0A = *(const float4*)&wA[(KL)];                           \
    float4 c1A = *(const float4*)&wA[(KL) + 4];                       \
    float4 c0B = *(const float4*)&wB[(KL)];                           \
    float4 c1B = *(const float4*)&wB[(KL) + 4];                       \
    STEP(0, c0A.x, c0B.x);                                            \
    STEP(1, c0A.y, c0B.y);                                            \
    REFILL(K0, 0); REFILL(K0, 1);                                     \
    STEP(2, c0A.z, c0B.z);                                            \
    STEP(3, c0A.w, c0B.w);                                            \
    REFILL(K0, 2); REFILL(K0, 3);                                     \
    STEP(4, c1A.x, c1B.x);                                            \
    STEP(5, c1A.y, c1B.y);                                            \
    REFILL(K0, 4); REFILL(K0, 5);                                     \
    STEP(6, c1A.z, c1B.z);                                            \
    STEP(7, c1A.w, c1B.w);                                            \
    REFILL(K0, 6); REFILL(K0, 7);                                     \
} while (0)

// ============================================================================
// Kernel A: partial strided-correlation GEMM
//   Tpart[kc][b][o][t] = sum over this block's q-chunk of
//       conv_w[o, c*2048+q] * xpad[b, c, 2q+t]
// Block: 288 threads (9 warps) = 32 o-rows x 9 t-cols. Thread: 2o x 8t.
// x window: 8-pair register ring fed by conflict-free padded LDS.64.
// Weights: cp.async double-buffered smem tiles (32 k each), broadcast LDS.
// ============================================================================
__global__ __launch_bounds__(288, 3)
void gemm_partial_kernel(const float* __restrict__ x,
                         const float* __restrict__ conv_w) {
    __shared__ __align__(16) float xsp[XSPLEN];
    __shared__ __align__(16) float ws[2 * WS_BUF];   // 22.5 KB

    const int otile = blockIdx.x;   // 0..7  -> 64 o's each
    const int b     = blockIdx.y;   // 0..3
    const int kc    = blockIdx.z;   // 0..15 -> 256 q each

    const int tid = threadIdx.x;
    const int k0  = kc * QCHUNK;
    const int ci  = k0 >> 11;       // channel for this chunk
    const int qq0 = k0 & 2047;      // q offset within channel
    const int obase = otile * 64;

    // Stage x slice (padded layout): xsp[f(j)] = xpad[b, ci, 2*qq0 + j]
    const float* xrow = x + (b * CCH + ci) * SLEN;
    for (int i = tid; i < XSLEN; i += 288) {
        int g = 2 * qq0 + i;
        xsp[XF(i)] = (g < SLEN) ? xrow[g] : 0.0f;
    }

    const int row  = tid / 9;        // 0..31
    const int col  = tid - row * 9;  // 0..8
    const int t0   = col * 8;        // 0,8,...,64
    const int row2 = row * 2;

    // weight staging: tile t covers k [k0 + t*32, +32); 512 16B-chunks/tile
    const float* wsrc = conv_w + (size_t)obase * 4096 + k0;
    // prologue: tiles 0 and 1
    #pragma unroll
    for (int pt = 0; pt < 2; pt++) {
        for (int c = tid; c < 512; c += 288) {
            int o = c >> 3, q4 = (c & 7) << 2;
            cp_async16(smem_u32(&ws[pt * WS_BUF + o * WS_STRIDE + q4]),
                       wsrc + (size_t)o * 4096 + pt * KTILE + q4);
        }
        CP_COMMIT();
    }

    __syncthreads();   // xsp published (cp.async still in flight)

    // init ring: pairs 0..7 cover raw x indices t0 .. t0+15
    unsigned long long R[8];
    #pragma unroll
    for (int i = 0; i < 8; i++)
        R[i] = *(const unsigned long long*)&xsp[XF(t0 + 2 * i)];

    unsigned long long accA0=0, accA1=0, accA2=0, accA3=0;
    unsigned long long accB0=0, accB1=0, accB2=0, accB3=0;

    #pragma unroll 1
    for (int t = 0; t < 8; t++) {
        CP_WAIT1();        // tile t's staging complete (only newest may pend)
        __syncthreads();   // publish tile t to all warps

        const float* wA = ws + (t & 1) * WS_BUF + row2 * WS_STRIDE;
        const float* wB = wA + WS_STRIDE;
        const int kb = t * KTILE;

        GROUP8S(kb,      0);
        GROUP8S(kb + 8,  8);
        GROUP8S(kb + 16, 16);
        GROUP8S(kb + 24, 24);

        __syncthreads();   // all warps done with buffer (t&1)
        if (t + 2 < 8) {
            for (int c = tid; c < 512; c += 288) {
                int o = c >> 3, q4 = (c & 7) << 2;
                cp_async16(smem_u32(&ws[(t & 1) * WS_BUF + o * WS_STRIDE + q4]),
                           wsrc + (size_t)o * 4096 + (t + 2) * KTILE + q4);
            }
        }
        CP_COMMIT();       // always commit (keeps wait_group bookkeeping exact)
    }

    // write partials: Tpart[kc][b][o][t]
    float* tp = g_Tpart + ((size_t)(kc * BQ + b) * OUTC) * TDIM;
    {
        float* dst = tp + (size_t)(obase + row2) * TDIM + t0;
        float2 v;
        v = unpack2(accA0); dst[0] = v.x; dst[1] = v.y;
        v = unpack2(accA1); dst[2] = v.x; dst[3] = v.y;
        v = unpack2(accA2); dst[4] = v.x; dst[5] = v.y;
        v = unpack2(accA3); dst[6] = v.x; dst[7] = v.y;
        dst += TDIM;
        v = unpack2(accB0); dst[0] = v.x; dst[1] = v.y;
        v = unpack2(accB1); dst[2] = v.x; dst[3] = v.y;
        v = unpack2(accB2); dst[4] = v.x; dst[5] = v.y;
        v = unpack2(accB3); dst[6] = v.x; dst[7] = v.y;
    }
}

// ============================================================================
// Kernel B: split-K reduction (fully coalesced)
// ============================================================================
__global__ __launch_bounds__(256)
void reduce_kernel() {
    int i = blockIdx.x * 256 + threadIdx.x;   // grid sized exactly
    float s = 0.0f;
    #pragma unroll
    for (int ks = 0; ks < KSPLIT; ks++)
        s += g_Tpart[(size_t)ks * (BQ * OUTC * TDIM) + i];
    g_Tred[i] = s;
}

// ============================================================================
// Kernel C: epilogue (4 bo per block)
//   out[b,o, p*2048 + m*32 + l] = relu( stft_w[l,m] * T[b,o,p+m] + conv_b[o] )
// ============================================================================
#define BO_PER_BLK 4
__global__ __launch_bounds__(256)
void epilogue_kernel(const float* __restrict__ stft_w,
                     const float* __restrict__ conv_b,
                     float* __restrict__ out) {
    __shared__ __align__(16) float swT[64 * SWROW];   // transposed: swT[m*36 + l]
    __shared__ float Ts[BO_PER_BLK * TDIM];           // 288
    __shared__ float biasS[BO_PER_BLK];

    const int bo0 = blockIdx.x * BO_PER_BLK;
    const int tid = threadIdx.x;

    for (int i = tid; i < 2048; i += 256) {
        int l = i >> 6, m = i & 63;
        swT[m * SWROW + l] = stft_w[i];
    }
    for (int i = tid; i < BO_PER_BLK * TDIM; i += 256)
        Ts[i] = g_Tred[(size_t)bo0 * TDIM + i];
    if (tid < BO_PER_BLK)
        biasS[tid] = conv_b[(bo0 + tid) & (OUTC - 1)];
    __syncthreads();

    #pragma unroll
    for (int jb = 0; jb < BO_PER_BLK; jb++) {
        const float bias = biasS[jb];
        float4* out4 = (float4*)(out + (size_t)(bo0 + jb) * 4096);
        const float* TsRow = &Ts[jb * TDIM];
        #pragma unroll
        for (int it = 0; it < 4; it++) {
            int q  = tid + it * 256;      // quad index; s' = 4*q
            int sp = q * 4;
            int p  = sp >> 11;
            int m  = (sp >> 5) & 63;
            int l0 = sp & 31;             // multiple of 4
            float tv = TsRow[p + m];
            float4 sw = *(const float4*)&swT[m * SWROW + l0];
            float4 r;
            r.x = fmaxf(fmaf(sw.x, tv, bias), 0.0f);
            r.y = fmaxf(fmaf(sw.y, tv, bias), 0.0f);
            r.z = fmaxf(fmaf(sw.z, tv, bias), 0.0f);
            r.w = fmaxf(fmaf(sw.w, tv, bias), 0.0f);
            out4[q] = r;
        }
    }
}

// ============================================================================
extern "C" void kernel_launch(void* const* d_in, const int* in_sizes, int n_in,
                              void* d_out, int out_size) {
    const float* x      = nullptr;
    const float* stft_w = nullptr;
    const float* conv_w = nullptr;
    const float* conv_b = nullptr;
    for (int i = 0; i < n_in; i++) {
        switch (in_sizes[i]) {
            case BQ * CCH * SLEN:  x      = (const float*)d_in[i]; break;  // 32768
            case NKF * KW:         stft_w = (const float*)d_in[i]; break;  // 2048
            case OUTC * 4096:      conv_w = (const float*)d_in[i]; break;  // 2097152
            case OUTC:             conv_b = (const float*)d_in[i]; break;  // 512
        }
    }

    gemm_partial_kernel<<<dim3(8, BQ, KSPLIT), 288>>>(x, conv_w);
    reduce_kernel<<<(BQ * OUTC * TDIM) / 256, 256>>>();
    epilogue_kernel<<<(BQ * OUTC) / BO_PER_BLK, 256>>>(stft_w, conv_b, (float*)d_out);
}